// round 11
// baseline (speedup 1.0000x reference)
#include <cuda_runtime.h>
#include <cstdint>

#define BB   2
#define GG   2
#define CIN  192
#define COUT 384
#define OG   192
#define HH   48
#define WW   48
#define LL   2304
#define KK   25
#define CKK  4800
#define REP  96

#define BM 192
#define BN 64
#define BK 32
#define NKT   (CKK / BK)   // 150 k-chunks
#define JITER (NKT / 2)    // 75 per team

// Fragment-ordered A stage: [mg(12)][kk(4)][lane(32)][w(4)] = 6144 floats (24KB)
// Pair-interleaved B stage:  [kk(4)][pix(64)][tig(4)][p(2)] = 2048 floats (8KB)
#define A_FLOATS 6144
#define B_FLOATS 2048
#define STG_FLOATS (A_FLOATS + B_FLOATS)          // 8192
#define SMEM_BYTES (2 * 3 * STG_FLOATS * 4)       // 196608 (2 teams x 3 stages)

#define WTX_PER_BG (NKT * A_FLOATS)               // 921600
#define WBLKS (BB * GG * WTX_PER_BG / 256)        // 14400 transform blocks
#define MBLKS 36                                  // mask blocks (36*256 = 9216)

// Pre-transformed weights, fragment order (one 16B read = one thread's A frag)
__device__ float g_wtx[BB * GG * WTX_PER_BG];
// 50-bit topo-causal mask per (b, g_out, l): bit (g_in*25 + tap).
__device__ unsigned long long g_mbits[BB * GG * LL];

// Fused prep: weight fragment-transform + topo mask build.
__global__ void prep_kernel(const int* __restrict__ topo, const float* __restrict__ dkw) {
    int bid = blockIdx.x;
    if (bid < WBLKS) {
        int idx = bid * 256 + threadIdx.x;
        int w = idx & 3;
        int lane = (idx >> 2) & 31;
        int kk = (idx >> 7) & 3;
        int rest = idx >> 9;
        int mg = rest % 12;
        int rest2 = rest / 12;
        int ch = rest2 % NKT;
        int bg = rest2 / NKT;
        int gid = lane >> 2, tig = lane & 3;
        int row = mg * 16 + gid + ((w & 1) << 3);
        int k = ch * 32 + kk * 8 + tig + ((w >> 1) << 2);
        g_wtx[idx] = dkw[((size_t)(bg * OG + row)) * CKK + k];
        return;
    }
    int idx = (bid - WBLKS) * 256 + threadIdx.x;  // 0..9215
    int l = idx % LL;
    int g = (idx / LL) % GG;
    int b = idx / (LL * GG);
    int y = l / WW, x = l % WW;
    int center = topo[(b * GG + g) * LL + l];
    unsigned long long m = 0ull;
#pragma unroll
    for (int gi = 0; gi < GG; gi++) {
        const int* tg = topo + (b * GG + gi) * LL;
#pragma unroll
        for (int t = 0; t < KK; t++) {
            int yy = y + t / 5 - 2;
            int xx = x + t % 5 - 2;
            // zero padding is always "future" -> false; in-bounds is raw int compare
            if ((unsigned)yy < HH && (unsigned)xx < WW && tg[yy * WW + xx] < center)
                m |= (1ull << (gi * KK + t));
        }
    }
    g_mbits[idx] = m;
}

__device__ __forceinline__ void mma_tf32(float c[4], const uint32_t a[4],
                                         const uint32_t b[2]) {
    asm volatile(
        "mma.sync.aligned.m16n8k8.row.col.f32.tf32.tf32.f32 "
        "{%0,%1,%2,%3}, {%4,%5,%6,%7}, {%8,%9}, {%0,%1,%2,%3};"
        : "+f"(c[0]), "+f"(c[1]), "+f"(c[2]), "+f"(c[3])
        : "r"(a[0]), "r"(a[1]), "r"(a[2]), "r"(a[3]), "r"(b[0]), "r"(b[1]));
}
__device__ __forceinline__ void cp16(uint32_t dst, const float* src) {
    asm volatile("cp.async.cg.shared.global [%0], [%1], 16;"
                 :: "r"(dst), "l"(src) : "memory");
}
__device__ __forceinline__ void cp4z(uint32_t dst, const float* src, uint32_t sz) {
    asm volatile("cp.async.ca.shared.global [%0], [%1], 4, %2;"
                 :: "r"(dst), "l"(src), "r"(sz) : "memory");
}
__device__ __forceinline__ void cp_commit() {
    asm volatile("cp.async.commit_group;" ::: "memory");
}
template <int N>
__device__ __forceinline__ void cp_wait() {
    asm volatile("cp.async.wait_group %0;" :: "n"(N) : "memory");
}

// Prefetch one k-chunk: A = fragment-ordered weights (pure coalesced copy),
// B = masked unfold gather with zfill into pair-interleaved layout.
__device__ __forceinline__ void prefetch_stage(
    uint32_t a_addr, const float* wsrc, const float* xb, int k0,
    int ttid, int pix, int kh, int l, unsigned long long mbits) {
#pragma unroll
    for (int it = 0; it < 6; it++)
        cp16(a_addr + (uint32_t)(ttid * 16 + it * 4096), wsrc + ttid * 4 + it * 1024);

    // B: 8 consecutive k (kh*8..kh*8+7) for this pixel, incremental addressing
    uint32_t b_addr = a_addr + A_FLOATS * 4;
    int i0 = k0 + kh * 8;
    unsigned ci = (unsigned)i0 / 25u;
    int tap = i0 - (int)ci * 25;
    int dy = tap / 5, dx = tap - dy * 5;
    const float* src = xb + ci * LL + l + dy * WW + dx - (2 * WW + 2);
    int bit = tap + ((int)ci >= REP ? 25 : 0);
    uint32_t dstb = b_addr + (uint32_t)((kh * 512 + pix * 8) * 4);
#pragma unroll
    for (int q = 0; q < 8; q++) {
        uint32_t sz = (uint32_t)((mbits >> bit) & 1ull) << 2;  // 4 or 0 (zfill)
        cp4z(dstb + (uint32_t)(((q & 3) * 2 + (q >> 2)) * 4), src, sz);
        tap++; bit++; src++; dx++;
        if (tap == 25) {            // channel boundary
            tap = 0; dx = 0; dy = 0; ci++;
            bit = ((int)ci >= REP) ? 25 : 0;
            src += LL - (4 * WW + 4) - 1;
        } else if (dx == 5) {       // kernel-row boundary
            dx = 0; dy++;
            src += WW - 5;
        }
    }
}

// One block: 192 out-channels x 64 pixels for one (b,g). 512 threads = 2 teams
// of 8 warps; team t handles k-chunks t, t+2, ... (split-K x2), triple-buffered
// cp.async pipeline each. Cross-team reduce via smem at the end.
__global__ __launch_bounds__(512, 1) void conv_mma_kernel(
    const float* __restrict__ x, const float* __restrict__ dkw,
    const float* __restrict__ dkb, float* __restrict__ out) {
    extern __shared__ float smem[];

    const int tid = threadIdx.x;
    const int team = tid >> 8;
    const int ttid = tid & 255;
    const int lane = tid & 31;
    const int twarp = ttid >> 5;  // 0..7
    const int bg = blockIdx.y;
    const int b = bg >> 1;
    const int l0 = blockIdx.x * BN;

    const float* xb = x + (size_t)b * CIN * LL;
    const float* wtx = g_wtx + (size_t)bg * WTX_PER_BG;

    const int pix = ttid & 63;
    const int kh = ttid >> 6;  // 0..3
    const int l = l0 + pix;
    const unsigned long long mbits = g_mbits[bg * LL + l];

    // warp tile: 48 (M=channels) x 32 (N=pixels)
    const int wn = (twarp & 1) * 32;
    const int mg0 = (twarp >> 1) * 3;  // first m16 group of this warp
    const int gid = lane >> 2;
    const int tig = lane & 3;

    float* Tb = smem + team * (3 * STG_FLOATS);

    float acc[3][4][4];
#pragma unroll
    for (int mi = 0; mi < 3; mi++)
#pragma unroll
        for (int ni = 0; ni < 4; ni++)
#pragma unroll
            for (int q = 0; q < 4; q++) acc[mi][ni][q] = 0.f;

    // ---- prologue: prime stages 0,1 ----
#pragma unroll
    for (int c = 0; c < 2; c++) {
        int ch = team + 2 * c;
        prefetch_stage((uint32_t)__cvta_generic_to_shared(Tb + c * STG_FLOATS),
                       wtx + (size_t)ch * A_FLOATS, xb, ch * BK, ttid, pix, kh, l, mbits);
        cp_commit();
    }

#pragma unroll 3
    for (int j = 0; j < JITER; j++) {
        cp_wait<1>();     // stage j%3 landed
        __syncthreads();  // publish; all warps done reading stage (j+2)%3
        if (j + 2 < JITER) {
            int ch = team + 2 * (j + 2);
            prefetch_stage(
                (uint32_t)__cvta_generic_to_shared(Tb + ((j + 2) % 3) * STG_FLOATS),
                wtx + (size_t)ch * A_FLOATS, xb, ch * BK, ttid, pix, kh, l, mbits);
        }
        cp_commit();  // empty at tail keeps group counts aligned

        const float* As = Tb + (j % 3) * STG_FLOATS;
        const float* Bsf = As + A_FLOATS;
#pragma unroll
        for (int kk = 0; kk < 4; kk++) {
            uint4 afr[3];
#pragma unroll
            for (int mi = 0; mi < 3; mi++)
                afr[mi] = *(const uint4*)(As + ((mg0 + mi) * 4 + kk) * 128 + lane * 4);
            uint2 bfr[4];
#pragma unroll
            for (int ni = 0; ni < 4; ni++) {
                int col = wn + ni * 8 + gid;
                bfr[ni] = *(const uint2*)(Bsf + kk * 512 + col * 8 + tig * 2);
            }
#pragma unroll
            for (int mi = 0; mi < 3; mi++)
#pragma unroll
                for (int ni = 0; ni < 4; ni++)
                    mma_tf32(acc[mi][ni], (const uint32_t*)&afr[mi],
                             (const uint32_t*)&bfr[ni]);
        }
    }

    // ---- drain, then cross-team reduction through smem ----
    cp_wait<0>();
    __syncthreads();

    float* red = smem;  // reuse stage memory: 256 threads * 52 words
    if (team == 1) {
#pragma unroll
        for (int mi = 0; mi < 3; mi++)
#pragma unroll
            for (int ni = 0; ni < 4; ni++)
                *(float4*)(red + ttid * 52 + (mi * 4 + ni) * 4) =
                    make_float4(acc[mi][ni][0], acc[mi][ni][1],
                                acc[mi][ni][2], acc[mi][ni][3]);
    }
    __syncthreads();

    if (team == 0) {
        const int g = bg & 1;
        const float* bias = dkb + bg * OG;
        float* outbg = out + (size_t)(b * COUT + g * OG) * LL + l0;
#pragma unroll
        for (int mi = 0; mi < 3; mi++) {
            int r0 = mg0 * 16 + mi * 16 + gid;
            int r1 = r0 + 8;
            float b0 = bias[r0], b1 = bias[r1];
#pragma unroll
            for (int ni = 0; ni < 4; ni++) {
                float4 o2 = *(const float4*)(red + ttid * 52 + (mi * 4 + ni) * 4);
                int col = wn + ni * 8 + tig * 2;
                float2 v0 = make_float2(acc[mi][ni][0] + o2.x + b0,
                                        acc[mi][ni][1] + o2.y + b0);
                float2 v1 = make_float2(acc[mi][ni][2] + o2.z + b1,
                                        acc[mi][ni][3] + o2.w + b1);
                *(float2*)(outbg + (size_t)r0 * LL + col) = v0;
                *(float2*)(outbg + (size_t)r1 * LL + col) = v1;
            }
        }
    }
}

extern "C" void kernel_launch(void* const* d_in, const int* in_sizes, int n_in,
                              void* d_out, int out_size) {
    const float* x = (const float*)d_in[0];
    const int* topo = (const int*)d_in[1];
    const float* dkw = (const float*)d_in[2];
    const float* dkb = (const float*)d_in[3];
    float* out = (float*)d_out;

    static bool attr_set = false;
    if (!attr_set) {
        cudaFuncSetAttribute(conv_mma_kernel,
                             cudaFuncAttributeMaxDynamicSharedMemorySize, SMEM_BYTES);
        attr_set = true;
    }

    prep_kernel<<<WBLKS + MBLKS, 256>>>(topo, dkw);

    dim3 grid(LL / BN, BB * GG);  // 36 x 4 = 144 blocks (~one wave on 148 SMs)
    conv_mma_kernel<<<grid, 512, SMEM_BYTES>>>(x, dkw, dkb, out);
}